// round 1
// baseline (speedup 1.0000x reference)
#include <cuda_runtime.h>

// Capsule routing, restructured:
//   round0: s1 = (u@w)/O + bias ; v1 = squash(s1)
//   round1: s2[b,o] = sum_i u[b,i] w[i,o] softmax_o(u[b,i] w[i,o] v1[b,o]) + bias ; v2 = squash(s2)
//   round2: same with Vacc = v1+v2 ; out = squash(...)
// Heavy kernel: warp = (b, 32-i chunk), lane owns 32 o-columns (o = 128k+4*lane+j),
// private register accumulators, per-chunk partials reduced by fused reduce+squash.

#define BB 64
#define II 1024
#define OO 1024
#define ICHUNK 32
#define NCHUNK (II / ICHUNK)   // 32
#define WPB 8                  // warps (distinct b) per block -> shared w rows hit L1
#define LOG2E 1.4426950408889634f

__device__ float g_partial[NCHUNK * BB * OO];  // 8 MB scratch
__device__ float g_vacc[BB * OO];              // accumulated v (pre-scaled by LOG2E)

__device__ __forceinline__ float ex2_approx(float x) {
    float r;
    asm("ex2.approx.f32 %0, %1;" : "=f"(r) : "f"(x));
    return r;
}

// MODE 0: uniform c = 1/O (pure scaled GEMV sweep). MODE 1: softmax routing using g_vacc.
template <int MODE>
__global__ void __launch_bounds__(WPB * 32, 1)
heavy_kernel(const float* __restrict__ u, const float* __restrict__ w) {
    const int warp  = threadIdx.x >> 5;
    const int lane  = threadIdx.x & 31;
    const int chunk = blockIdx.x;              // i-chunk: 0..31
    const int b     = blockIdx.y * WPB + warp; // 0..63
    const int i0    = chunk * ICHUNK;

    float V[32];
    if (MODE == 1) {
        const float4* v4p = reinterpret_cast<const float4*>(&g_vacc[b * OO]);
#pragma unroll
        for (int k = 0; k < 8; k++) {
            float4 v = v4p[k * 32 + lane];
            V[4 * k + 0] = v.x; V[4 * k + 1] = v.y;
            V[4 * k + 2] = v.z; V[4 * k + 3] = v.w;
        }
    }

    float acc[32];
#pragma unroll
    for (int k = 0; k < 32; k++) acc[k] = 0.0f;

    // each lane preloads one u value for the chunk; broadcast per-i via shfl
    const float au = u[b * II + i0 + lane];

    for (int ii = 0; ii < ICHUNK; ii++) {
        const float a = __shfl_sync(0xffffffffu, au, ii);
        const float4* wrow = reinterpret_cast<const float4*>(w + (size_t)(i0 + ii) * OO);

        if (MODE == 0) {
            const float aO = a * (1.0f / OO);
#pragma unroll
            for (int k = 0; k < 8; k++) {
                float4 wv = wrow[k * 32 + lane];
                acc[4 * k + 0] = fmaf(aO, wv.x, acc[4 * k + 0]);
                acc[4 * k + 1] = fmaf(aO, wv.y, acc[4 * k + 1]);
                acc[4 * k + 2] = fmaf(aO, wv.z, acc[4 * k + 2]);
                acc[4 * k + 3] = fmaf(aO, wv.w, acc[4 * k + 3]);
            }
        } else {
            float p[32];
            float esum = 0.0f;
#pragma unroll
            for (int k = 0; k < 8; k++) {
                float4 wv = wrow[k * 32 + lane];
                {
                    float t0 = a * wv.x;
                    float e  = ex2_approx(t0 * V[4 * k + 0]);  // V pre-scaled by LOG2E
                    esum += e; p[4 * k + 0] = t0 * e;
                }
                {
                    float t0 = a * wv.y;
                    float e  = ex2_approx(t0 * V[4 * k + 1]);
                    esum += e; p[4 * k + 1] = t0 * e;
                }
                {
                    float t0 = a * wv.z;
                    float e  = ex2_approx(t0 * V[4 * k + 2]);
                    esum += e; p[4 * k + 2] = t0 * e;
                }
                {
                    float t0 = a * wv.w;
                    float e  = ex2_approx(t0 * V[4 * k + 3]);
                    esum += e; p[4 * k + 3] = t0 * e;
                }
            }
            // softmax denominator: warp-level reduction across all 1024 o
#pragma unroll
            for (int s = 16; s > 0; s >>= 1)
                esum += __shfl_xor_sync(0xffffffffu, esum, s);
            const float rZ = 1.0f / esum;
#pragma unroll
            for (int k = 0; k < 32; k++) acc[k] = fmaf(p[k], rZ, acc[k]);
        }
    }

    float4* dst = reinterpret_cast<float4*>(&g_partial[((size_t)chunk * BB + b) * OO]);
#pragma unroll
    for (int k = 0; k < 8; k++) {
        float4 o4;
        o4.x = acc[4 * k + 0]; o4.y = acc[4 * k + 1];
        o4.z = acc[4 * k + 2]; o4.w = acc[4 * k + 3];
        dst[k * 32 + lane] = o4;
    }
}

// Sum the 32 chunk partials + bias, squash per row; write to g_vacc (scaled,
// optionally accumulated) or to outp when non-null.
__global__ void __launch_bounds__(256, 1)
reduce_squash_kernel(const float* __restrict__ bias, float* __restrict__ outp,
                     float scale, int accumulate) {
    const int b   = blockIdx.x;
    const int tid = threadIdx.x;

    float x[4];
#pragma unroll
    for (int k = 0; k < 4; k++) {
        const int o = tid + 256 * k;
        float s = bias[o];
#pragma unroll
        for (int c = 0; c < 32; c++)
            s += g_partial[((size_t)c * BB + b) * OO + o];
        x[k] = s;
    }

    float ss = x[0] * x[0] + x[1] * x[1] + x[2] * x[2] + x[3] * x[3];
#pragma unroll
    for (int s = 16; s > 0; s >>= 1)
        ss += __shfl_xor_sync(0xffffffffu, ss, s);

    __shared__ float red[8];
    if ((tid & 31) == 0) red[tid >> 5] = ss;
    __syncthreads();

    float n2 = 0.0f;
#pragma unroll
    for (int r = 0; r < 8; r++) n2 += red[r];

    const float n = sqrtf(n2);
    const float f = n2 / ((1.0f + n2) * (n + 1e-5f)) * scale;

    float* dst = outp ? outp : g_vacc;
#pragma unroll
    for (int k = 0; k < 4; k++) {
        const int o = tid + 256 * k;
        float val = x[k] * f;
        if (accumulate) val += dst[b * OO + o];
        dst[b * OO + o] = val;
    }
}

extern "C" void kernel_launch(void* const* d_in, const int* in_sizes, int n_in,
                              void* d_out, int out_size) {
    const float* u    = (const float*)d_in[0];
    const float* w    = (const float*)d_in[1];
    const float* bias = (const float*)d_in[2];
    float* out = (float*)d_out;

    dim3 grid(NCHUNK, BB / WPB);
    const int tpb = WPB * 32;

    // round 0: uniform coupling -> v1 (stored as v1*LOG2E in g_vacc)
    heavy_kernel<0><<<grid, tpb>>>(u, w);
    reduce_squash_kernel<<<BB, 256>>>(bias, nullptr, LOG2E, 0);

    // round 1: softmax routing with v1 -> v2 ; g_vacc += v2*LOG2E
    heavy_kernel<1><<<grid, tpb>>>(u, w);
    reduce_squash_kernel<<<BB, 256>>>(bias, nullptr, LOG2E, 1);

    // round 2: softmax routing with v1+v2 -> final squash to output
    heavy_kernel<1><<<grid, tpb>>>(u, w);
    reduce_squash_kernel<<<BB, 256>>>(bias, out, 1.0f, 0);
}

// round 2
// speedup vs baseline: 1.1065x; 1.1065x over previous
#include <cuda_runtime.h>

// Capsule routing, restructured:
//   round0: s1 = (u@w)/O + bias ; v1 = squash(s1)
//   round1: s2[b,o] = sum_i u[b,i] w[i,o] softmax_o(u[b,i] w[i,o] v1[b,o]) + bias ; v2 = squash(s2)
//   round2: same with Vacc = v1+v2 ; out = squash(...)
// Heavy kernel: warp = (b, 32-i chunk); lane owns 32 o (o = 128k+4*lane+j).
// Packed f32x2 math; exp via MUFU ex2 (75%) + deg-4 exp2 poly on FMA pipe (25%).
// Results accumulated into g_s via red.global.add; fused reduce+squash rezeroes g_s.

#define BB 64
#define II 1024
#define OO 1024
#define ICHUNK 32
#define NCHUNK (II / ICHUNK)   // 32
#define WPB 8
#define LOG2E 1.4426950408889634f

typedef unsigned long long u64;

__device__ float g_s[BB * OO];     // per-round accumulator (kept zero between launches)
__device__ float g_vacc[BB * OO];  // accumulated v (pre-scaled by LOG2E)

__device__ __forceinline__ float ex2a(float x) {
    float r; asm("ex2.approx.f32 %0, %1;" : "=f"(r) : "f"(x)); return r;
}
__device__ __forceinline__ float rcpa(float x) {
    float r; asm("rcp.approx.f32 %0, %1;" : "=f"(r) : "f"(x)); return r;
}
__device__ __forceinline__ u64 pk(float x, float y) {
    u64 r; asm("mov.b64 %0, {%1, %2};" : "=l"(r) : "f"(x), "f"(y)); return r;
}
__device__ __forceinline__ void upk(float& x, float& y, u64 v) {
    asm("mov.b64 {%0, %1}, %2;" : "=f"(x), "=f"(y) : "l"(v));
}
__device__ __forceinline__ u64 mul2(u64 a, u64 b) {
    u64 r; asm("mul.rn.f32x2 %0, %1, %2;" : "=l"(r) : "l"(a), "l"(b)); return r;
}
__device__ __forceinline__ u64 add2(u64 a, u64 b) {
    u64 r; asm("add.rn.f32x2 %0, %1, %2;" : "=l"(r) : "l"(a), "l"(b)); return r;
}
__device__ __forceinline__ u64 fma2(u64 a, u64 b, u64 c) {
    u64 r; asm("fma.rn.f32x2 %0, %1, %2, %3;" : "=l"(r) : "l"(a), "l"(b), "l"(c)); return r;
}

// packed exp2 for small |x| (deg-4 Taylor of 2^x); error < 1e-8 for |x| < 0.15
__device__ __forceinline__ u64 exp2p(u64 x, u64 C4, u64 C3, u64 C2, u64 C1, u64 ONE) {
    u64 r = fma2(C4, x, C3);
    r = fma2(r, x, C2);
    r = fma2(r, x, C1);
    r = fma2(r, x, ONE);
    return r;
}

// MODE 0: uniform c = 1/O (scaled GEMV). MODE 1: softmax routing vs g_vacc (LOG2E-scaled).
template <int MODE>
__global__ void __launch_bounds__(WPB * 32, 2)
heavy_kernel(const float* __restrict__ u, const float* __restrict__ w) {
    __shared__ float4 sV4[WPB * 256];  // 8 warps x 1024 floats = 32KB

    const int warp  = threadIdx.x >> 5;
    const int lane  = threadIdx.x & 31;
    const int chunk = blockIdx.x;
    const int b     = blockIdx.y * WPB + warp;
    const int i0    = chunk * ICHUNK;

    if (MODE == 1) {
        const float4* v4p = reinterpret_cast<const float4*>(&g_vacc[b * OO]);
#pragma unroll
        for (int k = 0; k < 8; k++)
            sV4[warp * 256 + k * 32 + lane] = v4p[k * 32 + lane];
    }
    __syncwarp();

    u64 acc[16];
#pragma unroll
    for (int m = 0; m < 16; m++) acc[m] = 0ull;

    const float au = u[b * II + i0 + lane];

    const u64 C4  = pk(0.00961813f, 0.00961813f);
    const u64 C3  = pk(0.05550411f, 0.05550411f);
    const u64 C2  = pk(0.24022651f, 0.24022651f);
    const u64 C1  = pk(0.69314718f, 0.69314718f);
    const u64 ONE = pk(1.0f, 1.0f);

    for (int ii = 0; ii < ICHUNK; ii++) {
        const float a = __shfl_sync(0xffffffffu, au, ii);
        const float4* wrow = reinterpret_cast<const float4*>(w + (size_t)(i0 + ii) * OO);

        if (MODE == 0) {
            const float aO = a * (1.0f / OO);
            const u64 aO2 = pk(aO, aO);
#pragma unroll
            for (int k = 0; k < 8; k++) {
                float4 wv = wrow[k * 32 + lane];
                u64 w01 = pk(wv.x, wv.y), w23 = pk(wv.z, wv.w);
                acc[2 * k + 0] = fma2(aO2, w01, acc[2 * k + 0]);
                acc[2 * k + 1] = fma2(aO2, w23, acc[2 * k + 1]);
            }
        } else {
            const u64 a2 = pk(a, a);
            u64 p[16];
            u64 esum2 = 0ull;
#pragma unroll
            for (int k = 0; k < 8; k++) {
                float4 wv = wrow[k * 32 + lane];
                float4 vv = sV4[warp * 256 + k * 32 + lane];
                u64 w01 = pk(wv.x, wv.y), w23 = pk(wv.z, wv.w);
                u64 v01 = pk(vv.x, vv.y), v23 = pk(vv.z, vv.w);
                u64 t01 = mul2(a2, w01), t23 = mul2(a2, w23);
                u64 l01 = mul2(t01, v01), l23 = mul2(t23, v23);
                u64 e01, e23;
                if (k < 6) {  // MUFU path (24 of 32 elems)
                    float x0, x1, y0, y1;
                    upk(x0, x1, l01); upk(y0, y1, l23);
                    e01 = pk(ex2a(x0), ex2a(x1));
                    e23 = pk(ex2a(y0), ex2a(y1));
                } else {      // FMA-pipe poly path (8 of 32 elems)
                    e01 = exp2p(l01, C4, C3, C2, C1, ONE);
                    e23 = exp2p(l23, C4, C3, C2, C1, ONE);
                }
                esum2 = add2(esum2, add2(e01, e23));
                p[2 * k + 0] = mul2(t01, e01);
                p[2 * k + 1] = mul2(t23, e23);
            }
            float e0, e1;
            upk(e0, e1, esum2);
            float es = e0 + e1;
#pragma unroll
            for (int s = 16; s > 0; s >>= 1)
                es += __shfl_xor_sync(0xffffffffu, es, s);
            const float rZ = rcpa(es);
            const u64 rZ2 = pk(rZ, rZ);
#pragma unroll
            for (int m = 0; m < 16; m++)
                acc[m] = fma2(p[m], rZ2, acc[m]);
        }
    }

    // accumulate into g_s via reduction atomics (no return value -> REDG)
    float* gs = &g_s[b * OO];
#pragma unroll
    for (int k = 0; k < 8; k++) {
        float f0, f1, f2, f3;
        upk(f0, f1, acc[2 * k + 0]);
        upk(f2, f3, acc[2 * k + 1]);
        const int o = 128 * k + 4 * lane;
        atomicAdd(&gs[o + 0], f0);
        atomicAdd(&gs[o + 1], f1);
        atomicAdd(&gs[o + 2], f2);
        atomicAdd(&gs[o + 3], f3);
    }
}

// Read g_s (+bias), squash per row, write g_vacc (scaled / accumulated) or outp.
// Rezeroes g_s so the next heavy launch can accumulate into it.
__global__ void __launch_bounds__(256, 1)
reduce_squash_kernel(const float* __restrict__ bias, float* __restrict__ outp,
                     float scale, int accumulate) {
    const int b   = blockIdx.x;
    const int tid = threadIdx.x;

    float x[4];
#pragma unroll
    for (int k = 0; k < 4; k++) {
        const int o = tid + 256 * k;
        x[k] = g_s[b * OO + o] + bias[o];
        g_s[b * OO + o] = 0.0f;
    }

    float ss = x[0] * x[0] + x[1] * x[1] + x[2] * x[2] + x[3] * x[3];
#pragma unroll
    for (int s = 16; s > 0; s >>= 1)
        ss += __shfl_xor_sync(0xffffffffu, ss, s);

    __shared__ float red[8];
    if ((tid & 31) == 0) red[tid >> 5] = ss;
    __syncthreads();

    float n2 = 0.0f;
#pragma unroll
    for (int r = 0; r < 8; r++) n2 += red[r];

    const float n = sqrtf(n2);
    const float f = n2 / ((1.0f + n2) * (n + 1e-5f)) * scale;

    float* dst = outp ? outp : g_vacc;
#pragma unroll
    for (int k = 0; k < 4; k++) {
        const int o = tid + 256 * k;
        float val = x[k] * f;
        if (accumulate) val += dst[b * OO + o];
        dst[b * OO + o] = val;
    }
}

extern "C" void kernel_launch(void* const* d_in, const int* in_sizes, int n_in,
                              void* d_out, int out_size) {
    const float* u    = (const float*)d_in[0];
    const float* w    = (const float*)d_in[1];
    const float* bias = (const float*)d_in[2];
    float* out = (float*)d_out;

    dim3 grid(NCHUNK, BB / WPB);
    const int tpb = WPB * 32;

    // round 0: uniform coupling -> v1 (stored as v1*LOG2E)
    heavy_kernel<0><<<grid, tpb>>>(u, w);
    reduce_squash_kernel<<<BB, 256>>>(bias, nullptr, LOG2E, 0);

    // round 1: softmax routing with v1 -> g_vacc += v2*LOG2E
    heavy_kernel<1><<<grid, tpb>>>(u, w);
    reduce_squash_kernel<<<BB, 256>>>(bias, nullptr, LOG2E, 1);

    // round 2: softmax routing with v1+v2 -> final squash to output
    heavy_kernel<1><<<grid, tpb>>>(u, w);
    reduce_squash_kernel<<<BB, 256>>>(bias, out, 1.0f, 0);
}